// round 13
// baseline (speedup 1.0000x reference)
#include <cuda_runtime.h>
#include <cuda_bf16.h>
#include <cuda_fp16.h>
#include <cstdint>

// ---------------------------------------------------------------------------
// GAT 2-layer fused pipeline (round 10).
// - Tensor-core split-bf16 GEMM, fused alpha epilogue, fp16 feature output.
// - Aggregation: batch-then-gather warp loop (coalesced ssrc/as + shfl
//   broadcast; MLP~8 on feature gathers), fp32 accumulate.
// - CSR build: R5-proven chain.
// ---------------------------------------------------------------------------

#define MAXN 50176
#define MAXM 870400

__device__ __half g_h16[MAXN * 128];   // fp16 features (reused by both layers)
__device__ float g_t [MAXN * 128];     // layer1 aggregated output (fp32)
__device__ float g_as1[MAXN * 4];
__device__ float g_ad1[MAXN * 4];
__device__ float g_as2[MAXN];
__device__ float g_ad2[MAXN];
__device__ int   g_deg[MAXN + 8];
__device__ int   g_rs [MAXN + 8];
__device__ int   g_cur[MAXN + 8];
__device__ int   g_ssrc[MAXM];
__device__ int   g_part[512];
__device__ __nv_bfloat16 g_bh1[128 * 128];
__device__ __nv_bfloat16 g_bl1[128 * 128];
__device__ __nv_bfloat16 g_bh2[128 * 128];
__device__ __nv_bfloat16 g_bl2[128 * 128];

// ---------------------------------------------------------------------------
// CSR build
// ---------------------------------------------------------------------------

__global__ void init_deg_kernel(int* __restrict__ deg, int N) {
    int i = blockIdx.x * blockDim.x + threadIdx.x;
    if (i < N) deg[i] = 1;             // self loop pre-counted
}

__global__ void hist_kernel(const int* __restrict__ dst, int E, int* __restrict__ deg) {
    int i4 = (blockIdx.x * blockDim.x + threadIdx.x) * 4;
    if (i4 + 3 < E) {
        int4 d = *(const int4*)&dst[i4];
        atomicAdd(&deg[d.x], 1);
        atomicAdd(&deg[d.y], 1);
        atomicAdd(&deg[d.z], 1);
        atomicAdd(&deg[d.w], 1);
    } else {
        for (int j = i4; j < E && j < i4 + 4; j++) atomicAdd(&deg[dst[j]], 1);
    }
}

__global__ void scan_partials(const int* __restrict__ deg, int N, int* __restrict__ part) {
    __shared__ int sm[512];
    int gid = blockIdx.x * 512 + threadIdx.x;
    sm[threadIdx.x] = (gid < N) ? deg[gid] : 0;
    __syncthreads();
    for (int off = 256; off; off >>= 1) {
        if (threadIdx.x < off) sm[threadIdx.x] += sm[threadIdx.x + off];
        __syncthreads();
    }
    if (threadIdx.x == 0) part[blockIdx.x] = sm[0];
}

// scan_final with inline spine: every block re-scans the (<=128) partials.
__global__ void scan_final(const int* __restrict__ deg, const int* __restrict__ part,
                           int nchunk, int N, int* __restrict__ rs, int* __restrict__ cur) {
    __shared__ int sp[128];
    __shared__ int sm[512];
    if (threadIdx.x < 128)
        sp[threadIdx.x] = (threadIdx.x < (unsigned)nchunk) ? part[threadIdx.x] : 0;
    __syncthreads();
    for (int off = 1; off < 128; off <<= 1) {
        int u = (threadIdx.x < 128 && threadIdx.x >= (unsigned)off) ? sp[threadIdx.x - off] : 0;
        __syncthreads();
        if (threadIdx.x < 128) sp[threadIdx.x] += u;
        __syncthreads();
    }
    int blkoff = (blockIdx.x > 0) ? sp[blockIdx.x - 1] : 0;

    int gid = blockIdx.x * 512 + threadIdx.x;
    int v = (gid < N) ? deg[gid] : 0;
    sm[threadIdx.x] = v;
    __syncthreads();
    for (int off = 1; off < 512; off <<= 1) {
        int t = (threadIdx.x >= (unsigned)off) ? sm[threadIdx.x - off] : 0;
        __syncthreads();
        sm[threadIdx.x] += t;
        __syncthreads();
    }
    if (gid < N) {
        int incl = sm[threadIdx.x] + blkoff;
        rs[gid + 1] = incl;
        cur[gid] = incl - v;
        if (gid == 0) rs[0] = 0;
    }
}

__global__ void scatter_kernel(const int* __restrict__ src, const int* __restrict__ dst,
                               int E, int N, int* __restrict__ cur, int* __restrict__ ssrc) {
    int i = blockIdx.x * blockDim.x + threadIdx.x;
    int M = E + N;
    if (i >= M) return;
    int s, d;
    if (i < E) { s = src[i]; d = dst[i]; }
    else       { s = d = i - E; }
    int pos = atomicAdd(&cur[d], 1);
    ssrc[pos] = s;
}

// ---------------------------------------------------------------------------
// Weight split (both layers): W[k][n] fp32 -> BhT/BlT[n][k] bf16 hi+lo
// ---------------------------------------------------------------------------

__global__ void bsplit_kernel(const float* __restrict__ W1, const float* __restrict__ W2,
                              __nv_bfloat16* __restrict__ Bh1, __nv_bfloat16* __restrict__ Bl1,
                              __nv_bfloat16* __restrict__ Bh2, __nv_bfloat16* __restrict__ Bl2) {
    int gid = blockIdx.x * 256 + threadIdx.x;   // 32768 total
    const float* W = (gid < 16384) ? W1 : W2;
    __nv_bfloat16* Bh = (gid < 16384) ? Bh1 : Bh2;
    __nv_bfloat16* Bl = (gid < 16384) ? Bl1 : Bl2;
    int idx = gid & 16383;
    int k = idx >> 7, n = idx & 127;
    float v = W[idx];
    __nv_bfloat16 h = __float2bfloat16_rn(v);
    __nv_bfloat16 l = __float2bfloat16_rn(v - __bfloat162float(h));
    Bh[n * 128 + k] = h;
    Bl[n * 128 + k] = l;
}

// ---------------------------------------------------------------------------
// Tensor-core SGEMM with fused alpha epilogue; features stored ONLY as fp16.
// ---------------------------------------------------------------------------

__device__ __forceinline__ int sidx(int r, int p) {
    return r * 16 + ((p + 2 * (r & 7)) & 15);
}

__device__ __forceinline__ void mma16816(float* c, const uint32_t* a, const uint32_t* b) {
    asm volatile(
        "mma.sync.aligned.m16n8k16.row.col.f32.bf16.bf16.f32 "
        "{%0,%1,%2,%3}, {%4,%5,%6,%7}, {%8,%9}, {%0,%1,%2,%3};"
        : "+f"(c[0]), "+f"(c[1]), "+f"(c[2]), "+f"(c[3])
        : "r"(a[0]), "r"(a[1]), "r"(a[2]), "r"(a[3]), "r"(b[0]), "r"(b[1]));
}

__device__ __forceinline__ uint32_t packbf(__nv_bfloat16 lo, __nv_bfloat16 hi) {
    __nv_bfloat162 t = __halves2bfloat162(lo, hi);
    return *(uint32_t*)&t;
}

template<int H>
__global__ void __launch_bounds__(256) gemm_tc_kernel(
    const float* __restrict__ A,
    const __nv_bfloat16* __restrict__ BhT,
    const __nv_bfloat16* __restrict__ BlT,
    const float* __restrict__ att_s,
    const float* __restrict__ att_d,
    __half* __restrict__ C16,
    float* __restrict__ as_out,
    float* __restrict__ ad_out,
    int N)
{
    __shared__ uint32_t AsH[128 * 16];
    __shared__ uint32_t AsL[128 * 16];
    __shared__ float sAS[128];
    __shared__ float sAD[128];

    int tid  = threadIdx.x;
    int warp = tid >> 5, lane = tid & 31;
    int qt = lane & 3, g = lane >> 2;
    int row0 = blockIdx.x * 128;
    int mrow = (warp >> 2) * 64;
    int ncol = (warp & 3) * 32;
    int head = warp & 3;

    if (H == 1 && tid < 128) { sAS[tid] = 0.f; sAD[tid] = 0.f; }

    float acc[4][4][4];
#pragma unroll
    for (int mt = 0; mt < 4; mt++)
#pragma unroll
        for (int nt = 0; nt < 4; nt++)
#pragma unroll
            for (int r = 0; r < 4; r++) acc[mt][nt][r] = 0.f;

    for (int s = 0; s < 4; s++) {
#pragma unroll
        for (int l = 0; l < 4; l++) {
            int idx = l * 256 + tid;
            int r = idx >> 3, f = idx & 7;
            int gr = row0 + r;
            float4 v = make_float4(0.f, 0.f, 0.f, 0.f);
            if (gr < N) v = *(const float4*)&A[(size_t)gr * 128 + s * 32 + f * 4];
            __nv_bfloat16 hx = __float2bfloat16_rn(v.x);
            __nv_bfloat16 hy = __float2bfloat16_rn(v.y);
            __nv_bfloat16 hz = __float2bfloat16_rn(v.z);
            __nv_bfloat16 hw = __float2bfloat16_rn(v.w);
            AsH[sidx(r, f * 2)]     = packbf(hx, hy);
            AsH[sidx(r, f * 2 + 1)] = packbf(hz, hw);
            __nv_bfloat16 lx = __float2bfloat16_rn(v.x - __bfloat162float(hx));
            __nv_bfloat16 ly = __float2bfloat16_rn(v.y - __bfloat162float(hy));
            __nv_bfloat16 lz = __float2bfloat16_rn(v.z - __bfloat162float(hz));
            __nv_bfloat16 lw = __float2bfloat16_rn(v.w - __bfloat162float(hw));
            AsL[sidx(r, f * 2)]     = packbf(lx, ly);
            AsL[sidx(r, f * 2 + 1)] = packbf(lz, lw);
        }
        __syncthreads();

#pragma unroll
        for (int cc = 0; cc < 2; cc++) {
            uint32_t ah[4][4], al[4][4];
            int p0 = cc * 8 + qt;
#pragma unroll
            for (int mt = 0; mt < 4; mt++) {
                int r0 = mrow + mt * 16 + g;
                ah[mt][0] = AsH[sidx(r0,     p0)];
                ah[mt][1] = AsH[sidx(r0 + 8, p0)];
                ah[mt][2] = AsH[sidx(r0,     p0 + 4)];
                ah[mt][3] = AsH[sidx(r0 + 8, p0 + 4)];
                al[mt][0] = AsL[sidx(r0,     p0)];
                al[mt][1] = AsL[sidx(r0 + 8, p0)];
                al[mt][2] = AsL[sidx(r0,     p0 + 4)];
                al[mt][3] = AsL[sidx(r0 + 8, p0 + 4)];
            }
            uint32_t bh[4][2], bl[4][2];
            int kg = s * 32 + cc * 16 + 2 * qt;
#pragma unroll
            for (int nt = 0; nt < 4; nt++) {
                const __nv_bfloat16* bp = BhT + (size_t)(ncol + nt * 8 + g) * 128 + kg;
                bh[nt][0] = *(const uint32_t*)bp;
                bh[nt][1] = *(const uint32_t*)(bp + 8);
                const __nv_bfloat16* lp = BlT + (size_t)(ncol + nt * 8 + g) * 128 + kg;
                bl[nt][0] = *(const uint32_t*)lp;
                bl[nt][1] = *(const uint32_t*)(lp + 8);
            }
#pragma unroll
            for (int mt = 0; mt < 4; mt++)
#pragma unroll
                for (int nt = 0; nt < 4; nt++) {
                    mma16816(acc[mt][nt], ah[mt], bh[nt]);
                    mma16816(acc[mt][nt], ah[mt], bl[nt]);
                    mma16816(acc[mt][nt], al[mt], bh[nt]);
                }
        }
        __syncthreads();
    }

    // epilogue: write fp16 C + fused alpha (from fp32 fragments)
#pragma unroll
    for (int mt = 0; mt < 4; mt++) {
        int row = row0 + mrow + mt * 16 + g;
        float ps0 = 0.f, pd0 = 0.f, ps1 = 0.f, pd1 = 0.f;
#pragma unroll
        for (int nt = 0; nt < 4; nt++) {
            int col = ncol + nt * 8 + 2 * qt;
            if (row < N)
                *(__half2*)&C16[(size_t)row * 128 + col] =
                    __float22half2_rn(make_float2(acc[mt][nt][0], acc[mt][nt][1]));
            if (row + 8 < N)
                *(__half2*)&C16[(size_t)(row + 8) * 128 + col] =
                    __float22half2_rn(make_float2(acc[mt][nt][2], acc[mt][nt][3]));
            float a0 = __ldg(&att_s[col]), a1 = __ldg(&att_s[col + 1]);
            float d0 = __ldg(&att_d[col]), d1 = __ldg(&att_d[col + 1]);
            ps0 += acc[mt][nt][0] * a0 + acc[mt][nt][1] * a1;
            pd0 += acc[mt][nt][0] * d0 + acc[mt][nt][1] * d1;
            ps1 += acc[mt][nt][2] * a0 + acc[mt][nt][3] * a1;
            pd1 += acc[mt][nt][2] * d0 + acc[mt][nt][3] * d1;
        }
#pragma unroll
        for (int off = 1; off <= 2; off <<= 1) {
            ps0 += __shfl_xor_sync(0xFFFFFFFFu, ps0, off);
            pd0 += __shfl_xor_sync(0xFFFFFFFFu, pd0, off);
            ps1 += __shfl_xor_sync(0xFFFFFFFFu, ps1, off);
            pd1 += __shfl_xor_sync(0xFFFFFFFFu, pd1, off);
        }
        if (qt == 0) {
            if (H == 4) {
                if (row < N)     { as_out[(size_t)row * 4 + head] = ps0;
                                   ad_out[(size_t)row * 4 + head] = pd0; }
                if (row + 8 < N) { as_out[(size_t)(row + 8) * 4 + head] = ps1;
                                   ad_out[(size_t)(row + 8) * 4 + head] = pd1; }
            } else {
                int lr = mrow + mt * 16 + g;
                atomicAdd(&sAS[lr], ps0);
                atomicAdd(&sAD[lr], pd0);
                atomicAdd(&sAS[lr + 8], ps1);
                atomicAdd(&sAD[lr + 8], pd1);
            }
        }
    }
    if (H == 1) {
        __syncthreads();
        if (tid < 128 && row0 + tid < N) {
            as_out[row0 + tid] = sAS[tid];
            ad_out[row0 + tid] = sAD[tid];
        }
    }
}

// ---------------------------------------------------------------------------
// Warp-per-dst aggregation, batch-then-gather:
// batch phase computes softmax weights for B edges in parallel (coalesced
// ssrc + as loads, exp in parallel); serial phase broadcasts sr/w via shfl
// and issues the fp16 feature gathers back-to-back (high MLP).
// ---------------------------------------------------------------------------

__device__ __forceinline__ float lrelu(float x) { return x > 0.f ? x : 0.2f * x; }

template<int H>
__global__ void aggr_kernel(const __half* __restrict__ h16,
                            const float* __restrict__ as,
                            const float* __restrict__ ad,
                            const int* __restrict__ rs,
                            const int* __restrict__ ssrc,
                            const float* __restrict__ bias,
                            float* __restrict__ out,
                            int N, int do_relu)
{
    int node = (blockIdx.x * blockDim.x + threadIdx.x) >> 5;
    if (node >= N) return;
    int lane = threadIdx.x & 31;
    int s = rs[node], e = rs[node + 1];

    const int B = (H == 4) ? 8 : 32;       // edges per batch
    int head = (H == 4) ? (lane >> 3) : 0; // head this lane gathers for

    // ad for the head this lane COMPUTES in the batch phase
    float ad_b;
    if (H == 4) {
        float4 adv = *(const float4*)&ad[node * 4];
        int hh = lane & 3;
        ad_b = hh == 0 ? adv.x : hh == 1 ? adv.y : hh == 2 ? adv.z : adv.w;
    } else {
        ad_b = ad[node];
    }

    float4 acc = make_float4(0.f, 0.f, 0.f, 0.f);
    float den = 0.f;

    for (int base = s; base < e; base += B) {
        int m = e - base; if (m > B) m = B;
        // ---- batch phase: weights for edges [base, base+m) ----
        int eoff = (H == 4) ? (lane >> 2) : lane;
        int idx = base + ((eoff < m) ? eoff : 0);
        int srv = __ldg(&ssrc[idx]);
        float av = (H == 4) ? __ldg(&as[srv * 4 + (lane & 3)]) : __ldg(&as[srv]);
        float wv = __expf(lrelu(av + ad_b));

        // ---- serial phase: gather + accumulate ----
        if (m == B) {
#pragma unroll
            for (int j = 0; j < B; j++) {
                int sr  = __shfl_sync(0xFFFFFFFFu, srv, (H == 4) ? j * 4 : j);
                float w = __shfl_sync(0xFFFFFFFFu, wv,  (H == 4) ? j * 4 + head : j);
                uint2 u = __ldcg((const uint2*)&h16[(size_t)sr * 128 + lane * 4]);
                float2 f0 = __half22float2(*(__half2*)&u.x);
                float2 f1 = __half22float2(*(__half2*)&u.y);
                acc.x = fmaf(w, f0.x, acc.x);
                acc.y = fmaf(w, f0.y, acc.y);
                acc.z = fmaf(w, f1.x, acc.z);
                acc.w = fmaf(w, f1.y, acc.w);
                den += w;
            }
        } else {
            for (int j = 0; j < m; j++) {
                int sr  = __shfl_sync(0xFFFFFFFFu, srv, (H == 4) ? j * 4 : j);
                float w = __shfl_sync(0xFFFFFFFFu, wv,  (H == 4) ? j * 4 + head : j);
                uint2 u = __ldcg((const uint2*)&h16[(size_t)sr * 128 + lane * 4]);
                float2 f0 = __half22float2(*(__half2*)&u.x);
                float2 f1 = __half22float2(*(__half2*)&u.y);
                acc.x = fmaf(w, f0.x, acc.x);
                acc.y = fmaf(w, f0.y, acc.y);
                acc.z = fmaf(w, f1.x, acc.z);
                acc.w = fmaf(w, f1.y, acc.w);
                den += w;
            }
        }
    }

    float inv = 1.0f / den;
    float4 bb = *(const float4*)&bias[lane * 4];
    float4 o;
    o.x = acc.x * inv + bb.x;
    o.y = acc.y * inv + bb.y;
    o.z = acc.z * inv + bb.z;
    o.w = acc.w * inv + bb.w;
    if (do_relu) {
        o.x = fmaxf(o.x, 0.f); o.y = fmaxf(o.y, 0.f);
        o.z = fmaxf(o.z, 0.f); o.w = fmaxf(o.w, 0.f);
    }
    *(float4*)&out[(size_t)node * 128 + lane * 4] = o;
}

// ---------------------------------------------------------------------------

extern "C" void kernel_launch(void* const* d_in, const int* in_sizes, int n_in,
                              void* d_out, int out_size) {
    const float* x    = (const float*)d_in[0];
    const int*   ei   = (const int*)  d_in[1];
    const float* W1   = (const float*)d_in[2];
    const float* aS1  = (const float*)d_in[3];
    const float* aD1  = (const float*)d_in[4];
    const float* b1   = (const float*)d_in[5];
    const float* W2   = (const float*)d_in[6];
    const float* aS2  = (const float*)d_in[7];
    const float* aD2  = (const float*)d_in[8];
    const float* b2   = (const float*)d_in[9];

    int N = in_sizes[0] / 128;
    int E = in_sizes[1] / 2;
    int M = E + N;

    float *t, *as1, *ad1, *as2, *ad2;
    __half *h16;
    int *deg, *rs, *cur, *ssrc, *part;
    __nv_bfloat16 *bh1, *bl1, *bh2, *bl2;
    cudaGetSymbolAddress((void**)&h16, g_h16);
    cudaGetSymbolAddress((void**)&t,   g_t);
    cudaGetSymbolAddress((void**)&as1, g_as1);
    cudaGetSymbolAddress((void**)&ad1, g_ad1);
    cudaGetSymbolAddress((void**)&as2, g_as2);
    cudaGetSymbolAddress((void**)&ad2, g_ad2);
    cudaGetSymbolAddress((void**)&deg, g_deg);
    cudaGetSymbolAddress((void**)&rs,  g_rs);
    cudaGetSymbolAddress((void**)&cur, g_cur);
    cudaGetSymbolAddress((void**)&ssrc,g_ssrc);
    cudaGetSymbolAddress((void**)&part,g_part);
    cudaGetSymbolAddress((void**)&bh1, g_bh1);
    cudaGetSymbolAddress((void**)&bl1, g_bl1);
    cudaGetSymbolAddress((void**)&bh2, g_bh2);
    cudaGetSymbolAddress((void**)&bl2, g_bl2);

    const int* src = ei;
    const int* dst = ei + E;

    int nchunk = (N + 511) / 512;

    bsplit_kernel<<<128, 256>>>(W1, W2, bh1, bl1, bh2, bl2);
    init_deg_kernel<<<(N + 255) / 256, 256>>>(deg, N);
    hist_kernel<<<(E / 4 + 256) / 256, 256>>>(dst, E, deg);
    scan_partials<<<nchunk, 512>>>(deg, N, part);
    scan_final<<<nchunk, 512>>>(deg, part, nchunk, N, rs, cur);
    scatter_kernel<<<(M + 255) / 256, 256>>>(src, dst, E, N, cur, ssrc);

    int gemm_blocks = (N + 127) / 128;
    int warp_blocks = (N * 32 + 255) / 256;

    // layer 1
    gemm_tc_kernel<4><<<gemm_blocks, 256>>>(x, bh1, bl1, aS1, aD1, h16, as1, ad1, N);
    aggr_kernel<4><<<warp_blocks, 256>>>(h16, as1, ad1, rs, ssrc, b1, t, N, 1);

    // layer 2
    gemm_tc_kernel<1><<<gemm_blocks, 256>>>(t, bh2, bl2, aS2, aD2, h16, as2, ad2, N);
    aggr_kernel<1><<<warp_blocks, 256>>>(h16, as2, ad2, rs, ssrc, b2, (float*)d_out, N, 0);
}

// round 14
// speedup vs baseline: 1.0825x; 1.0825x over previous
#include <cuda_runtime.h>
#include <cuda_bf16.h>
#include <cuda_fp16.h>
#include <cstdint>

// ---------------------------------------------------------------------------
// GAT 2-layer fused pipeline (round 14).
// - Tensor-core split-bf16 GEMM, fused alpha epilogue, fp16 feature output.
// - Aggregation: R9-proven simple loop (fp16 gathers, fp32 accumulate).
// - CSR chain forked onto a second stream, overlapped with bsplit+gemm1.
// ---------------------------------------------------------------------------

#define MAXN 50176
#define MAXM 870400

__device__ __half g_h16[MAXN * 128];   // fp16 features (reused by both layers)
__device__ float g_t [MAXN * 128];     // layer1 aggregated output (fp32)
__device__ float g_as1[MAXN * 4];
__device__ float g_ad1[MAXN * 4];
__device__ float g_as2[MAXN];
__device__ float g_ad2[MAXN];
__device__ int   g_deg[MAXN + 8];
__device__ int   g_rs [MAXN + 8];
__device__ int   g_cur[MAXN + 8];
__device__ int   g_ssrc[MAXM];
__device__ int   g_part[512];
__device__ __nv_bfloat16 g_bh1[128 * 128];
__device__ __nv_bfloat16 g_bl1[128 * 128];
__device__ __nv_bfloat16 g_bh2[128 * 128];
__device__ __nv_bfloat16 g_bl2[128 * 128];

// ---------------------------------------------------------------------------
// CSR build
// ---------------------------------------------------------------------------

__global__ void init_deg_kernel(int* __restrict__ deg, int N) {
    int i = blockIdx.x * blockDim.x + threadIdx.x;
    if (i < N) deg[i] = 1;             // self loop pre-counted
}

__global__ void hist_kernel(const int* __restrict__ dst, int E, int* __restrict__ deg) {
    int i4 = (blockIdx.x * blockDim.x + threadIdx.x) * 4;
    if (i4 + 3 < E) {
        int4 d = *(const int4*)&dst[i4];
        atomicAdd(&deg[d.x], 1);
        atomicAdd(&deg[d.y], 1);
        atomicAdd(&deg[d.z], 1);
        atomicAdd(&deg[d.w], 1);
    } else {
        for (int j = i4; j < E && j < i4 + 4; j++) atomicAdd(&deg[dst[j]], 1);
    }
}

__global__ void scan_partials(const int* __restrict__ deg, int N, int* __restrict__ part) {
    __shared__ int sm[512];
    int gid = blockIdx.x * 512 + threadIdx.x;
    sm[threadIdx.x] = (gid < N) ? deg[gid] : 0;
    __syncthreads();
    for (int off = 256; off; off >>= 1) {
        if (threadIdx.x < off) sm[threadIdx.x] += sm[threadIdx.x + off];
        __syncthreads();
    }
    if (threadIdx.x == 0) part[blockIdx.x] = sm[0];
}

// scan_final with inline spine: every block re-scans the (<=128) partials.
__global__ void scan_final(const int* __restrict__ deg, const int* __restrict__ part,
                           int nchunk, int N, int* __restrict__ rs, int* __restrict__ cur) {
    __shared__ int sp[128];
    __shared__ int sm[512];
    if (threadIdx.x < 128)
        sp[threadIdx.x] = (threadIdx.x < (unsigned)nchunk) ? part[threadIdx.x] : 0;
    __syncthreads();
    for (int off = 1; off < 128; off <<= 1) {
        int u = (threadIdx.x < 128 && threadIdx.x >= (unsigned)off) ? sp[threadIdx.x - off] : 0;
        __syncthreads();
        if (threadIdx.x < 128) sp[threadIdx.x] += u;
        __syncthreads();
    }
    int blkoff = (blockIdx.x > 0) ? sp[blockIdx.x - 1] : 0;

    int gid = blockIdx.x * 512 + threadIdx.x;
    int v = (gid < N) ? deg[gid] : 0;
    sm[threadIdx.x] = v;
    __syncthreads();
    for (int off = 1; off < 512; off <<= 1) {
        int t = (threadIdx.x >= (unsigned)off) ? sm[threadIdx.x - off] : 0;
        __syncthreads();
        sm[threadIdx.x] += t;
        __syncthreads();
    }
    if (gid < N) {
        int incl = sm[threadIdx.x] + blkoff;
        rs[gid + 1] = incl;
        cur[gid] = incl - v;
        if (gid == 0) rs[0] = 0;
    }
}

__global__ void scatter_kernel(const int* __restrict__ src, const int* __restrict__ dst,
                               int E, int N, int* __restrict__ cur, int* __restrict__ ssrc) {
    int i = blockIdx.x * blockDim.x + threadIdx.x;
    int M = E + N;
    if (i >= M) return;
    int s, d;
    if (i < E) { s = src[i]; d = dst[i]; }
    else       { s = d = i - E; }
    int pos = atomicAdd(&cur[d], 1);
    ssrc[pos] = s;
}

// ---------------------------------------------------------------------------
// Weight split (both layers): W[k][n] fp32 -> BhT/BlT[n][k] bf16 hi+lo
// ---------------------------------------------------------------------------

__global__ void bsplit_kernel(const float* __restrict__ W1, const float* __restrict__ W2,
                              __nv_bfloat16* __restrict__ Bh1, __nv_bfloat16* __restrict__ Bl1,
                              __nv_bfloat16* __restrict__ Bh2, __nv_bfloat16* __restrict__ Bl2) {
    int gid = blockIdx.x * 256 + threadIdx.x;   // 32768 total
    const float* W = (gid < 16384) ? W1 : W2;
    __nv_bfloat16* Bh = (gid < 16384) ? Bh1 : Bh2;
    __nv_bfloat16* Bl = (gid < 16384) ? Bl1 : Bl2;
    int idx = gid & 16383;
    int k = idx >> 7, n = idx & 127;
    float v = W[idx];
    __nv_bfloat16 h = __float2bfloat16_rn(v);
    __nv_bfloat16 l = __float2bfloat16_rn(v - __bfloat162float(h));
    Bh[n * 128 + k] = h;
    Bl[n * 128 + k] = l;
}

// ---------------------------------------------------------------------------
// Tensor-core SGEMM with fused alpha epilogue; features stored ONLY as fp16.
// ---------------------------------------------------------------------------

__device__ __forceinline__ int sidx(int r, int p) {
    return r * 16 + ((p + 2 * (r & 7)) & 15);
}

__device__ __forceinline__ void mma16816(float* c, const uint32_t* a, const uint32_t* b) {
    asm volatile(
        "mma.sync.aligned.m16n8k16.row.col.f32.bf16.bf16.f32 "
        "{%0,%1,%2,%3}, {%4,%5,%6,%7}, {%8,%9}, {%0,%1,%2,%3};"
        : "+f"(c[0]), "+f"(c[1]), "+f"(c[2]), "+f"(c[3])
        : "r"(a[0]), "r"(a[1]), "r"(a[2]), "r"(a[3]), "r"(b[0]), "r"(b[1]));
}

__device__ __forceinline__ uint32_t packbf(__nv_bfloat16 lo, __nv_bfloat16 hi) {
    __nv_bfloat162 t = __halves2bfloat162(lo, hi);
    return *(uint32_t*)&t;
}

template<int H>
__global__ void __launch_bounds__(256) gemm_tc_kernel(
    const float* __restrict__ A,
    const __nv_bfloat16* __restrict__ BhT,
    const __nv_bfloat16* __restrict__ BlT,
    const float* __restrict__ att_s,
    const float* __restrict__ att_d,
    __half* __restrict__ C16,
    float* __restrict__ as_out,
    float* __restrict__ ad_out,
    int N)
{
    __shared__ uint32_t AsH[128 * 16];
    __shared__ uint32_t AsL[128 * 16];
    __shared__ float sAS[128];
    __shared__ float sAD[128];

    int tid  = threadIdx.x;
    int warp = tid >> 5, lane = tid & 31;
    int qt = lane & 3, g = lane >> 2;
    int row0 = blockIdx.x * 128;
    int mrow = (warp >> 2) * 64;
    int ncol = (warp & 3) * 32;
    int head = warp & 3;

    if (H == 1 && tid < 128) { sAS[tid] = 0.f; sAD[tid] = 0.f; }

    float acc[4][4][4];
#pragma unroll
    for (int mt = 0; mt < 4; mt++)
#pragma unroll
        for (int nt = 0; nt < 4; nt++)
#pragma unroll
            for (int r = 0; r < 4; r++) acc[mt][nt][r] = 0.f;

    for (int s = 0; s < 4; s++) {
#pragma unroll
        for (int l = 0; l < 4; l++) {
            int idx = l * 256 + tid;
            int r = idx >> 3, f = idx & 7;
            int gr = row0 + r;
            float4 v = make_float4(0.f, 0.f, 0.f, 0.f);
            if (gr < N) v = *(const float4*)&A[(size_t)gr * 128 + s * 32 + f * 4];
            __nv_bfloat16 hx = __float2bfloat16_rn(v.x);
            __nv_bfloat16 hy = __float2bfloat16_rn(v.y);
            __nv_bfloat16 hz = __float2bfloat16_rn(v.z);
            __nv_bfloat16 hw = __float2bfloat16_rn(v.w);
            AsH[sidx(r, f * 2)]     = packbf(hx, hy);
            AsH[sidx(r, f * 2 + 1)] = packbf(hz, hw);
            __nv_bfloat16 lx = __float2bfloat16_rn(v.x - __bfloat162float(hx));
            __nv_bfloat16 ly = __float2bfloat16_rn(v.y - __bfloat162float(hy));
            __nv_bfloat16 lz = __float2bfloat16_rn(v.z - __bfloat162float(hz));
            __nv_bfloat16 lw = __float2bfloat16_rn(v.w - __bfloat162float(hw));
            AsL[sidx(r, f * 2)]     = packbf(lx, ly);
            AsL[sidx(r, f * 2 + 1)] = packbf(lz, lw);
        }
        __syncthreads();

#pragma unroll
        for (int cc = 0; cc < 2; cc++) {
            uint32_t ah[4][4], al[4][4];
            int p0 = cc * 8 + qt;
#pragma unroll
            for (int mt = 0; mt < 4; mt++) {
                int r0 = mrow + mt * 16 + g;
                ah[mt][0] = AsH[sidx(r0,     p0)];
                ah[mt][1] = AsH[sidx(r0 + 8, p0)];
                ah[mt][2] = AsH[sidx(r0,     p0 + 4)];
                ah[mt][3] = AsH[sidx(r0 + 8, p0 + 4)];
                al[mt][0] = AsL[sidx(r0,     p0)];
                al[mt][1] = AsL[sidx(r0 + 8, p0)];
                al[mt][2] = AsL[sidx(r0,     p0 + 4)];
                al[mt][3] = AsL[sidx(r0 + 8, p0 + 4)];
            }
            uint32_t bh[4][2], bl[4][2];
            int kg = s * 32 + cc * 16 + 2 * qt;
#pragma unroll
            for (int nt = 0; nt < 4; nt++) {
                const __nv_bfloat16* bp = BhT + (size_t)(ncol + nt * 8 + g) * 128 + kg;
                bh[nt][0] = *(const uint32_t*)bp;
                bh[nt][1] = *(const uint32_t*)(bp + 8);
                const __nv_bfloat16* lp = BlT + (size_t)(ncol + nt * 8 + g) * 128 + kg;
                bl[nt][0] = *(const uint32_t*)lp;
                bl[nt][1] = *(const uint32_t*)(lp + 8);
            }
#pragma unroll
            for (int mt = 0; mt < 4; mt++)
#pragma unroll
                for (int nt = 0; nt < 4; nt++) {
                    mma16816(acc[mt][nt], ah[mt], bh[nt]);
                    mma16816(acc[mt][nt], ah[mt], bl[nt]);
                    mma16816(acc[mt][nt], al[mt], bh[nt]);
                }
        }
        __syncthreads();
    }

    // epilogue: write fp16 C + fused alpha (from fp32 fragments)
#pragma unroll
    for (int mt = 0; mt < 4; mt++) {
        int row = row0 + mrow + mt * 16 + g;
        float ps0 = 0.f, pd0 = 0.f, ps1 = 0.f, pd1 = 0.f;
#pragma unroll
        for (int nt = 0; nt < 4; nt++) {
            int col = ncol + nt * 8 + 2 * qt;
            if (row < N)
                *(__half2*)&C16[(size_t)row * 128 + col] =
                    __float22half2_rn(make_float2(acc[mt][nt][0], acc[mt][nt][1]));
            if (row + 8 < N)
                *(__half2*)&C16[(size_t)(row + 8) * 128 + col] =
                    __float22half2_rn(make_float2(acc[mt][nt][2], acc[mt][nt][3]));
            float a0 = __ldg(&att_s[col]), a1 = __ldg(&att_s[col + 1]);
            float d0 = __ldg(&att_d[col]), d1 = __ldg(&att_d[col + 1]);
            ps0 += acc[mt][nt][0] * a0 + acc[mt][nt][1] * a1;
            pd0 += acc[mt][nt][0] * d0 + acc[mt][nt][1] * d1;
            ps1 += acc[mt][nt][2] * a0 + acc[mt][nt][3] * a1;
            pd1 += acc[mt][nt][2] * d0 + acc[mt][nt][3] * d1;
        }
#pragma unroll
        for (int off = 1; off <= 2; off <<= 1) {
            ps0 += __shfl_xor_sync(0xFFFFFFFFu, ps0, off);
            pd0 += __shfl_xor_sync(0xFFFFFFFFu, pd0, off);
            ps1 += __shfl_xor_sync(0xFFFFFFFFu, ps1, off);
            pd1 += __shfl_xor_sync(0xFFFFFFFFu, pd1, off);
        }
        if (qt == 0) {
            if (H == 4) {
                if (row < N)     { as_out[(size_t)row * 4 + head] = ps0;
                                   ad_out[(size_t)row * 4 + head] = pd0; }
                if (row + 8 < N) { as_out[(size_t)(row + 8) * 4 + head] = ps1;
                                   ad_out[(size_t)(row + 8) * 4 + head] = pd1; }
            } else {
                int lr = mrow + mt * 16 + g;
                atomicAdd(&sAS[lr], ps0);
                atomicAdd(&sAD[lr], pd0);
                atomicAdd(&sAS[lr + 8], ps1);
                atomicAdd(&sAD[lr + 8], pd1);
            }
        }
    }
    if (H == 1) {
        __syncthreads();
        if (tid < 128 && row0 + tid < N) {
            as_out[row0 + tid] = sAS[tid];
            ad_out[row0 + tid] = sAD[tid];
        }
    }
}

// ---------------------------------------------------------------------------
// Warp-per-dst single-pass segment softmax + aggregation (fp16 gathers,
// fp32 weights/accumulate). R9-proven form.
// ---------------------------------------------------------------------------

__device__ __forceinline__ float lrelu(float x) { return x > 0.f ? x : 0.2f * x; }

template<int H>
__global__ void aggr_kernel(const __half* __restrict__ h16,
                            const float* __restrict__ as,
                            const float* __restrict__ ad,
                            const int* __restrict__ rs,
                            const int* __restrict__ ssrc,
                            const float* __restrict__ bias,
                            float* __restrict__ out,
                            int N, int do_relu)
{
    int node = (blockIdx.x * blockDim.x + threadIdx.x) >> 5;
    if (node >= N) return;
    int lane = threadIdx.x & 31;
    int s = rs[node], e = rs[node + 1];

    int head = (H == 4) ? (lane >> 3) : 0;
    float my_ad = (H == 4) ? ad[node * 4 + head] : ad[node];

    float4 acc = make_float4(0.f, 0.f, 0.f, 0.f);
    float den = 0.f;
#pragma unroll 4
    for (int i = s; i < e; i++) {
        int sr = __ldg(&ssrc[i]);
        float a = __ldg(&as[sr * H + head]);
        float w = __expf(lrelu(a + my_ad));
        uint2 u = __ldcg((const uint2*)&h16[(size_t)sr * 128 + lane * 4]);
        float2 f0 = __half22float2(*(__half2*)&u.x);
        float2 f1 = __half22float2(*(__half2*)&u.y);
        acc.x = fmaf(w, f0.x, acc.x);
        acc.y = fmaf(w, f0.y, acc.y);
        acc.z = fmaf(w, f1.x, acc.z);
        acc.w = fmaf(w, f1.y, acc.w);
        den += w;
    }
    float inv = 1.0f / den;
    float4 bb = *(const float4*)&bias[lane * 4];
    float4 o;
    o.x = acc.x * inv + bb.x;
    o.y = acc.y * inv + bb.y;
    o.z = acc.z * inv + bb.z;
    o.w = acc.w * inv + bb.w;
    if (do_relu) {
        o.x = fmaxf(o.x, 0.f); o.y = fmaxf(o.y, 0.f);
        o.z = fmaxf(o.z, 0.f); o.w = fmaxf(o.w, 0.f);
    }
    *(float4*)&out[(size_t)node * 128 + lane * 4] = o;
}

// ---------------------------------------------------------------------------

extern "C" void kernel_launch(void* const* d_in, const int* in_sizes, int n_in,
                              void* d_out, int out_size) {
    const float* x    = (const float*)d_in[0];
    const int*   ei   = (const int*)  d_in[1];
    const float* W1   = (const float*)d_in[2];
    const float* aS1  = (const float*)d_in[3];
    const float* aD1  = (const float*)d_in[4];
    const float* b1   = (const float*)d_in[5];
    const float* W2   = (const float*)d_in[6];
    const float* aS2  = (const float*)d_in[7];
    const float* aD2  = (const float*)d_in[8];
    const float* b2   = (const float*)d_in[9];

    int N = in_sizes[0] / 128;
    int E = in_sizes[1] / 2;
    int M = E + N;

    float *t, *as1, *ad1, *as2, *ad2;
    __half *h16;
    int *deg, *rs, *cur, *ssrc, *part;
    __nv_bfloat16 *bh1, *bl1, *bh2, *bl2;
    cudaGetSymbolAddress((void**)&h16, g_h16);
    cudaGetSymbolAddress((void**)&t,   g_t);
    cudaGetSymbolAddress((void**)&as1, g_as1);
    cudaGetSymbolAddress((void**)&ad1, g_ad1);
    cudaGetSymbolAddress((void**)&as2, g_as2);
    cudaGetSymbolAddress((void**)&ad2, g_ad2);
    cudaGetSymbolAddress((void**)&deg, g_deg);
    cudaGetSymbolAddress((void**)&rs,  g_rs);
    cudaGetSymbolAddress((void**)&cur, g_cur);
    cudaGetSymbolAddress((void**)&ssrc,g_ssrc);
    cudaGetSymbolAddress((void**)&part,g_part);
    cudaGetSymbolAddress((void**)&bh1, g_bh1);
    cudaGetSymbolAddress((void**)&bl1, g_bl1);
    cudaGetSymbolAddress((void**)&bh2, g_bh2);
    cudaGetSymbolAddress((void**)&bl2, g_bl2);

    const int* src = ei;
    const int* dst = ei + E;

    int nchunk = (N + 511) / 512;

    // One-time host-side stream/event setup (outside capture: the harness's
    // correctness call happens before graph capture).
    static cudaStream_t s2 = nullptr;
    static cudaEvent_t ev_fork = nullptr, ev_join = nullptr;
    if (s2 == nullptr) {
        cudaStreamCreateWithFlags(&s2, cudaStreamNonBlocking);
        cudaEventCreateWithFlags(&ev_fork, cudaEventDisableTiming);
        cudaEventCreateWithFlags(&ev_join, cudaEventDisableTiming);
    }

    // Fork: CSR chain on s2, GEMM prep on the main stream (parallel branches
    // in the captured graph).
    cudaEventRecord(ev_fork, 0);
    cudaStreamWaitEvent(s2, ev_fork, 0);

    init_deg_kernel<<<(N + 255) / 256, 256, 0, s2>>>(deg, N);
    hist_kernel<<<(E / 4 + 256) / 256, 256, 0, s2>>>(dst, E, deg);
    scan_partials<<<nchunk, 512, 0, s2>>>(deg, N, part);
    scan_final<<<nchunk, 512, 0, s2>>>(deg, part, nchunk, N, rs, cur);
    scatter_kernel<<<(M + 255) / 256, 256, 0, s2>>>(src, dst, E, N, cur, ssrc);
    cudaEventRecord(ev_join, s2);

    int gemm_blocks = (N + 127) / 128;
    int warp_blocks = (N * 32 + 255) / 256;

    bsplit_kernel<<<128, 256>>>(W1, W2, bh1, bl1, bh2, bl2);
    gemm_tc_kernel<4><<<gemm_blocks, 256>>>(x, bh1, bl1, aS1, aD1, h16, as1, ad1, N);

    // Join: aggregation needs the CSR.
    cudaStreamWaitEvent(0, ev_join, 0);

    aggr_kernel<4><<<warp_blocks, 256>>>(h16, as1, ad1, rs, ssrc, b1, t, N, 1);

    // layer 2
    gemm_tc_kernel<1><<<gemm_blocks, 256>>>(t, bh2, bl2, aS2, aD2, h16, as2, ad2, N);
    aggr_kernel<1><<<warp_blocks, 256>>>(h16, as2, ad2, rs, ssrc, b2, (float*)d_out, N, 0);
}

// round 15
// speedup vs baseline: 1.0865x; 1.0036x over previous
#include <cuda_runtime.h>
#include <cuda_bf16.h>
#include <cuda_fp16.h>
#include <cstdint>

// ---------------------------------------------------------------------------
// GAT 2-layer fused pipeline (round 15).
// - Tensor-core split-bf16 GEMM, fused alpha epilogue, fp16 feature output.
// - Aggregation: R9-proven simple loop (fp16 gathers, fp32 accumulate).
// - CSR chain on second stream, overlapped with bsplit+gemm1:
//   memsetAsync + hist4 + ONE fused scan (self-loops emitted inline) +
//   int4-vectorized edge-only scatter.
// ---------------------------------------------------------------------------

#define MAXN 50176
#define MAXM 870400

__device__ __half g_h16[MAXN * 128];   // fp16 features (reused by both layers)
__device__ float g_t [MAXN * 128];     // layer1 aggregated output (fp32)
__device__ float g_as1[MAXN * 4];
__device__ float g_ad1[MAXN * 4];
__device__ float g_as2[MAXN];
__device__ float g_ad2[MAXN];
__device__ int   g_deg[MAXN + 8];
__device__ int   g_rs [MAXN + 8];
__device__ int   g_cur[MAXN + 8];
__device__ int   g_ssrc[MAXM];
__device__ __nv_bfloat16 g_bh1[128 * 128];
__device__ __nv_bfloat16 g_bl1[128 * 128];
__device__ __nv_bfloat16 g_bh2[128 * 128];
__device__ __nv_bfloat16 g_bl2[128 * 128];

// ---------------------------------------------------------------------------
// CSR build
// ---------------------------------------------------------------------------

__global__ void hist_kernel(const int* __restrict__ dst, int E, int* __restrict__ deg) {
    int i4 = (blockIdx.x * blockDim.x + threadIdx.x) * 4;
    if (i4 + 3 < E) {
        int4 d = *(const int4*)&dst[i4];
        atomicAdd(&deg[d.x], 1);
        atomicAdd(&deg[d.y], 1);
        atomicAdd(&deg[d.z], 1);
        atomicAdd(&deg[d.w], 1);
    } else {
        for (int j = i4; j < E && j < i4 + 4; j++) atomicAdd(&deg[dst[j]], 1);
    }
}

// Fused scan (one launch): block b sums all chunks before it (coalesced,
// L2-hot), then Kogge-Stones its own 512-chunk. Reads deg[i]+1 (self loop
// folded). Emits each node's self-loop into ssrc[start] and sets
// cur[node]=start+1, so scatter handles real edges only.
__global__ void __launch_bounds__(512) scan_fused_kernel(
    const int* __restrict__ deg, int N,
    int* __restrict__ rs, int* __restrict__ cur, int* __restrict__ ssrc)
{
    __shared__ int sm[512];
    int b = blockIdx.x;
    int base = b * 512;

    // phase 1: sum of (deg[i]+1) for i < base
    int pre = 0;
    for (int i = threadIdx.x; i < base; i += 512) pre += deg[i] + 1;
    sm[threadIdx.x] = pre;
    __syncthreads();
    for (int off = 256; off; off >>= 1) {
        if (threadIdx.x < off) sm[threadIdx.x] += sm[threadIdx.x + off];
        __syncthreads();
    }
    int blkoff = sm[0];
    __syncthreads();

    // phase 2: inclusive Kogge-Stone over this chunk
    int gid = base + threadIdx.x;
    int v = (gid < N) ? deg[gid] + 1 : 0;
    sm[threadIdx.x] = v;
    __syncthreads();
    for (int off = 1; off < 512; off <<= 1) {
        int t = (threadIdx.x >= (unsigned)off) ? sm[threadIdx.x - off] : 0;
        __syncthreads();
        sm[threadIdx.x] += t;
        __syncthreads();
    }
    if (gid < N) {
        int incl = sm[threadIdx.x] + blkoff;
        int start = incl - v;
        rs[gid + 1] = incl;
        ssrc[start] = gid;        // self loop emitted here
        cur[gid] = start + 1;
        if (gid == 0) rs[0] = 0;
    }
}

// Edge-only scatter, 4 edges/thread with int4 loads.
__global__ void scatter_kernel(const int* __restrict__ src, const int* __restrict__ dst,
                               int E, int* __restrict__ cur, int* __restrict__ ssrc) {
    int i4 = (blockIdx.x * blockDim.x + threadIdx.x) * 4;
    if (i4 + 3 < E) {
        int4 s = *(const int4*)&src[i4];
        int4 d = *(const int4*)&dst[i4];
        ssrc[atomicAdd(&cur[d.x], 1)] = s.x;
        ssrc[atomicAdd(&cur[d.y], 1)] = s.y;
        ssrc[atomicAdd(&cur[d.z], 1)] = s.z;
        ssrc[atomicAdd(&cur[d.w], 1)] = s.w;
    } else {
        for (int j = i4; j < E && j < i4 + 4; j++)
            ssrc[atomicAdd(&cur[dst[j]], 1)] = src[j];
    }
}

// ---------------------------------------------------------------------------
// Weight split (both layers): W[k][n] fp32 -> BhT/BlT[n][k] bf16 hi+lo
// ---------------------------------------------------------------------------

__global__ void bsplit_kernel(const float* __restrict__ W1, const float* __restrict__ W2,
                              __nv_bfloat16* __restrict__ Bh1, __nv_bfloat16* __restrict__ Bl1,
                              __nv_bfloat16* __restrict__ Bh2, __nv_bfloat16* __restrict__ Bl2) {
    int gid = blockIdx.x * 256 + threadIdx.x;   // 32768 total
    const float* W = (gid < 16384) ? W1 : W2;
    __nv_bfloat16* Bh = (gid < 16384) ? Bh1 : Bh2;
    __nv_bfloat16* Bl = (gid < 16384) ? Bl1 : Bl2;
    int idx = gid & 16383;
    int k = idx >> 7, n = idx & 127;
    float v = W[idx];
    __nv_bfloat16 h = __float2bfloat16_rn(v);
    __nv_bfloat16 l = __float2bfloat16_rn(v - __bfloat162float(h));
    Bh[n * 128 + k] = h;
    Bl[n * 128 + k] = l;
}

// ---------------------------------------------------------------------------
// Tensor-core SGEMM with fused alpha epilogue; features stored ONLY as fp16.
// ---------------------------------------------------------------------------

__device__ __forceinline__ int sidx(int r, int p) {
    return r * 16 + ((p + 2 * (r & 7)) & 15);
}

__device__ __forceinline__ void mma16816(float* c, const uint32_t* a, const uint32_t* b) {
    asm volatile(
        "mma.sync.aligned.m16n8k16.row.col.f32.bf16.bf16.f32 "
        "{%0,%1,%2,%3}, {%4,%5,%6,%7}, {%8,%9}, {%0,%1,%2,%3};"
        : "+f"(c[0]), "+f"(c[1]), "+f"(c[2]), "+f"(c[3])
        : "r"(a[0]), "r"(a[1]), "r"(a[2]), "r"(a[3]), "r"(b[0]), "r"(b[1]));
}

__device__ __forceinline__ uint32_t packbf(__nv_bfloat16 lo, __nv_bfloat16 hi) {
    __nv_bfloat162 t = __halves2bfloat162(lo, hi);
    return *(uint32_t*)&t;
}

template<int H>
__global__ void __launch_bounds__(256) gemm_tc_kernel(
    const float* __restrict__ A,
    const __nv_bfloat16* __restrict__ BhT,
    const __nv_bfloat16* __restrict__ BlT,
    const float* __restrict__ att_s,
    const float* __restrict__ att_d,
    __half* __restrict__ C16,
    float* __restrict__ as_out,
    float* __restrict__ ad_out,
    int N)
{
    __shared__ uint32_t AsH[128 * 16];
    __shared__ uint32_t AsL[128 * 16];
    __shared__ float sAS[128];
    __shared__ float sAD[128];

    int tid  = threadIdx.x;
    int warp = tid >> 5, lane = tid & 31;
    int qt = lane & 3, g = lane >> 2;
    int row0 = blockIdx.x * 128;
    int mrow = (warp >> 2) * 64;
    int ncol = (warp & 3) * 32;
    int head = warp & 3;

    if (H == 1 && tid < 128) { sAS[tid] = 0.f; sAD[tid] = 0.f; }

    float acc[4][4][4];
#pragma unroll
    for (int mt = 0; mt < 4; mt++)
#pragma unroll
        for (int nt = 0; nt < 4; nt++)
#pragma unroll
            for (int r = 0; r < 4; r++) acc[mt][nt][r] = 0.f;

    for (int s = 0; s < 4; s++) {
#pragma unroll
        for (int l = 0; l < 4; l++) {
            int idx = l * 256 + tid;
            int r = idx >> 3, f = idx & 7;
            int gr = row0 + r;
            float4 v = make_float4(0.f, 0.f, 0.f, 0.f);
            if (gr < N) v = *(const float4*)&A[(size_t)gr * 128 + s * 32 + f * 4];
            __nv_bfloat16 hx = __float2bfloat16_rn(v.x);
            __nv_bfloat16 hy = __float2bfloat16_rn(v.y);
            __nv_bfloat16 hz = __float2bfloat16_rn(v.z);
            __nv_bfloat16 hw = __float2bfloat16_rn(v.w);
            AsH[sidx(r, f * 2)]     = packbf(hx, hy);
            AsH[sidx(r, f * 2 + 1)] = packbf(hz, hw);
            __nv_bfloat16 lx = __float2bfloat16_rn(v.x - __bfloat162float(hx));
            __nv_bfloat16 ly = __float2bfloat16_rn(v.y - __bfloat162float(hy));
            __nv_bfloat16 lz = __float2bfloat16_rn(v.z - __bfloat162float(hz));
            __nv_bfloat16 lw = __float2bfloat16_rn(v.w - __bfloat162float(hw));
            AsL[sidx(r, f * 2)]     = packbf(lx, ly);
            AsL[sidx(r, f * 2 + 1)] = packbf(lz, lw);
        }
        __syncthreads();

#pragma unroll
        for (int cc = 0; cc < 2; cc++) {
            uint32_t ah[4][4], al[4][4];
            int p0 = cc * 8 + qt;
#pragma unroll
            for (int mt = 0; mt < 4; mt++) {
                int r0 = mrow + mt * 16 + g;
                ah[mt][0] = AsH[sidx(r0,     p0)];
                ah[mt][1] = AsH[sidx(r0 + 8, p0)];
                ah[mt][2] = AsH[sidx(r0,     p0 + 4)];
                ah[mt][3] = AsH[sidx(r0 + 8, p0 + 4)];
                al[mt][0] = AsL[sidx(r0,     p0)];
                al[mt][1] = AsL[sidx(r0 + 8, p0)];
                al[mt][2] = AsL[sidx(r0,     p0 + 4)];
                al[mt][3] = AsL[sidx(r0 + 8, p0 + 4)];
            }
            uint32_t bh[4][2], bl[4][2];
            int kg = s * 32 + cc * 16 + 2 * qt;
#pragma unroll
            for (int nt = 0; nt < 4; nt++) {
                const __nv_bfloat16* bp = BhT + (size_t)(ncol + nt * 8 + g) * 128 + kg;
                bh[nt][0] = *(const uint32_t*)bp;
                bh[nt][1] = *(const uint32_t*)(bp + 8);
                const __nv_bfloat16* lp = BlT + (size_t)(ncol + nt * 8 + g) * 128 + kg;
                bl[nt][0] = *(const uint32_t*)lp;
                bl[nt][1] = *(const uint32_t*)(lp + 8);
            }
#pragma unroll
            for (int mt = 0; mt < 4; mt++)
#pragma unroll
                for (int nt = 0; nt < 4; nt++) {
                    mma16816(acc[mt][nt], ah[mt], bh[nt]);
                    mma16816(acc[mt][nt], ah[mt], bl[nt]);
                    mma16816(acc[mt][nt], al[mt], bh[nt]);
                }
        }
        __syncthreads();
    }

    // epilogue: write fp16 C + fused alpha (from fp32 fragments)
#pragma unroll
    for (int mt = 0; mt < 4; mt++) {
        int row = row0 + mrow + mt * 16 + g;
        float ps0 = 0.f, pd0 = 0.f, ps1 = 0.f, pd1 = 0.f;
#pragma unroll
        for (int nt = 0; nt < 4; nt++) {
            int col = ncol + nt * 8 + 2 * qt;
            if (row < N)
                *(__half2*)&C16[(size_t)row * 128 + col] =
                    __float22half2_rn(make_float2(acc[mt][nt][0], acc[mt][nt][1]));
            if (row + 8 < N)
                *(__half2*)&C16[(size_t)(row + 8) * 128 + col] =
                    __float22half2_rn(make_float2(acc[mt][nt][2], acc[mt][nt][3]));
            float a0 = __ldg(&att_s[col]), a1 = __ldg(&att_s[col + 1]);
            float d0 = __ldg(&att_d[col]), d1 = __ldg(&att_d[col + 1]);
            ps0 += acc[mt][nt][0] * a0 + acc[mt][nt][1] * a1;
            pd0 += acc[mt][nt][0] * d0 + acc[mt][nt][1] * d1;
            ps1 += acc[mt][nt][2] * a0 + acc[mt][nt][3] * a1;
            pd1 += acc[mt][nt][2] * d0 + acc[mt][nt][3] * d1;
        }
#pragma unroll
        for (int off = 1; off <= 2; off <<= 1) {
            ps0 += __shfl_xor_sync(0xFFFFFFFFu, ps0, off);
            pd0 += __shfl_xor_sync(0xFFFFFFFFu, pd0, off);
            ps1 += __shfl_xor_sync(0xFFFFFFFFu, ps1, off);
            pd1 += __shfl_xor_sync(0xFFFFFFFFu, pd1, off);
        }
        if (qt == 0) {
            if (H == 4) {
                if (row < N)     { as_out[(size_t)row * 4 + head] = ps0;
                                   ad_out[(size_t)row * 4 + head] = pd0; }
                if (row + 8 < N) { as_out[(size_t)(row + 8) * 4 + head] = ps1;
                                   ad_out[(size_t)(row + 8) * 4 + head] = pd1; }
            } else {
                int lr = mrow + mt * 16 + g;
                atomicAdd(&sAS[lr], ps0);
                atomicAdd(&sAD[lr], pd0);
                atomicAdd(&sAS[lr + 8], ps1);
                atomicAdd(&sAD[lr + 8], pd1);
            }
        }
    }
    if (H == 1) {
        __syncthreads();
        if (tid < 128 && row0 + tid < N) {
            as_out[row0 + tid] = sAS[tid];
            ad_out[row0 + tid] = sAD[tid];
        }
    }
}

// ---------------------------------------------------------------------------
// Warp-per-dst single-pass segment softmax + aggregation (fp16 gathers,
// fp32 weights/accumulate). R9-proven form.
// ---------------------------------------------------------------------------

__device__ __forceinline__ float lrelu(float x) { return x > 0.f ? x : 0.2f * x; }

template<int H>
__global__ void aggr_kernel(const __half* __restrict__ h16,
                            const float* __restrict__ as,
                            const float* __restrict__ ad,
                            const int* __restrict__ rs,
                            const int* __restrict__ ssrc,
                            const float* __restrict__ bias,
                            float* __restrict__ out,
                            int N, int do_relu)
{
    int node = (blockIdx.x * blockDim.x + threadIdx.x) >> 5;
    if (node >= N) return;
    int lane = threadIdx.x & 31;
    int s = rs[node], e = rs[node + 1];

    int head = (H == 4) ? (lane >> 3) : 0;
    float my_ad = (H == 4) ? ad[node * 4 + head] : ad[node];

    float4 acc = make_float4(0.f, 0.f, 0.f, 0.f);
    float den = 0.f;
#pragma unroll 4
    for (int i = s; i < e; i++) {
        int sr = __ldg(&ssrc[i]);
        float a = __ldg(&as[sr * H + head]);
        float w = __expf(lrelu(a + my_ad));
        uint2 u = __ldcg((const uint2*)&h16[(size_t)sr * 128 + lane * 4]);
        float2 f0 = __half22float2(*(__half2*)&u.x);
        float2 f1 = __half22float2(*(__half2*)&u.y);
        acc.x = fmaf(w, f0.x, acc.x);
        acc.y = fmaf(w, f0.y, acc.y);
        acc.z = fmaf(w, f1.x, acc.z);
        acc.w = fmaf(w, f1.y, acc.w);
        den += w;
    }
    float inv = 1.0f / den;
    float4 bb = *(const float4*)&bias[lane * 4];
    float4 o;
    o.x = acc.x * inv + bb.x;
    o.y = acc.y * inv + bb.y;
    o.z = acc.z * inv + bb.z;
    o.w = acc.w * inv + bb.w;
    if (do_relu) {
        o.x = fmaxf(o.x, 0.f); o.y = fmaxf(o.y, 0.f);
        o.z = fmaxf(o.z, 0.f); o.w = fmaxf(o.w, 0.f);
    }
    *(float4*)&out[(size_t)node * 128 + lane * 4] = o;
}

// ---------------------------------------------------------------------------

extern "C" void kernel_launch(void* const* d_in, const int* in_sizes, int n_in,
                              void* d_out, int out_size) {
    const float* x    = (const float*)d_in[0];
    const int*   ei   = (const int*)  d_in[1];
    const float* W1   = (const float*)d_in[2];
    const float* aS1  = (const float*)d_in[3];
    const float* aD1  = (const float*)d_in[4];
    const float* b1   = (const float*)d_in[5];
    const float* W2   = (const float*)d_in[6];
    const float* aS2  = (const float*)d_in[7];
    const float* aD2  = (const float*)d_in[8];
    const float* b2   = (const float*)d_in[9];

    int N = in_sizes[0] / 128;
    int E = in_sizes[1] / 2;

    float *t, *as1, *ad1, *as2, *ad2;
    __half *h16;
    int *deg, *rs, *cur, *ssrc;
    __nv_bfloat16 *bh1, *bl1, *bh2, *bl2;
    cudaGetSymbolAddress((void**)&h16, g_h16);
    cudaGetSymbolAddress((void**)&t,   g_t);
    cudaGetSymbolAddress((void**)&as1, g_as1);
    cudaGetSymbolAddress((void**)&ad1, g_ad1);
    cudaGetSymbolAddress((void**)&as2, g_as2);
    cudaGetSymbolAddress((void**)&ad2, g_ad2);
    cudaGetSymbolAddress((void**)&deg, g_deg);
    cudaGetSymbolAddress((void**)&rs,  g_rs);
    cudaGetSymbolAddress((void**)&cur, g_cur);
    cudaGetSymbolAddress((void**)&ssrc,g_ssrc);
    cudaGetSymbolAddress((void**)&bh1, g_bh1);
    cudaGetSymbolAddress((void**)&bl1, g_bl1);
    cudaGetSymbolAddress((void**)&bh2, g_bh2);
    cudaGetSymbolAddress((void**)&bl2, g_bl2);

    const int* src = ei;
    const int* dst = ei + E;

    int nchunk = (N + 511) / 512;

    // One-time host-side stream/event setup.
    static cudaStream_t s2 = nullptr;
    static cudaEvent_t ev_fork = nullptr, ev_join = nullptr;
    if (s2 == nullptr) {
        cudaStreamCreateWithFlags(&s2, cudaStreamNonBlocking);
        cudaEventCreateWithFlags(&ev_fork, cudaEventDisableTiming);
        cudaEventCreateWithFlags(&ev_join, cudaEventDisableTiming);
    }

    // Fork: CSR chain on s2, GEMM prep on the main stream.
    cudaEventRecord(ev_fork, 0);
    cudaStreamWaitEvent(s2, ev_fork, 0);

    cudaMemsetAsync(deg, 0, (size_t)N * sizeof(int), s2);
    hist_kernel<<<(E / 4 + 256) / 256, 256, 0, s2>>>(dst, E, deg);
    scan_fused_kernel<<<nchunk, 512, 0, s2>>>(deg, N, rs, cur, ssrc);
    scatter_kernel<<<(E / 4 + 256) / 256, 256, 0, s2>>>(src, dst, E, cur, ssrc);
    cudaEventRecord(ev_join, s2);

    int gemm_blocks = (N + 127) / 128;
    int warp_blocks = (N * 32 + 255) / 256;

    bsplit_kernel<<<128, 256>>>(W1, W2, bh1, bl1, bh2, bl2);
    gemm_tc_kernel<4><<<gemm_blocks, 256>>>(x, bh1, bl1, aS1, aD1, h16, as1, ad1, N);

    // Join: aggregation needs the CSR.
    cudaStreamWaitEvent(0, ev_join, 0);

    aggr_kernel<4><<<warp_blocks, 256>>>(h16, as1, ad1, rs, ssrc, b1, t, N, 1);

    // layer 2
    gemm_tc_kernel<1><<<gemm_blocks, 256>>>(t, bh2, bl2, aS2, aD2, h16, as2, ad2, N);
    aggr_kernel<1><<<warp_blocks, 256>>>(h16, as2, ad2, rs, ssrc, b2, (float*)d_out, N, 0);
}